// round 14
// baseline (speedup 1.0000x reference)
#include <cuda_runtime.h>
#include <cuda_bf16.h>
#include <cstdint>

#define TN    8192
#define DD    512
#define NPER  4
#define KNN   5
#define NCAND 16                     // candidates per row per j-half

#define KM      128                  // rows per CTA (A persistent in smem)
#define KNT     128                  // j cols per tile
#define JHALF   (TN / 2)
#define NTILES  (JHALF / KNT)        // 32
#define KCHB    128                  // k bytes per B chunk (fp8: 128 k)
#define NCH     4                    // chunks per tile (4 x 128 k = 512)
#define NCHT    (NTILES * NCH)       // 128 global chunks
#define A_BYTES 65536                // 128 x 512 fp8, swizzled
#define B_T_B   16384                // 128 rows x 128 B
#define OFF_B   65536
#define OFF_D   98304
#define DSTRIDE 132
#define OFF_SQS (OFF_D + KM * DSTRIDE * 4)   // 165888
#define SMEM_TOTAL (OFF_SQS + 512)           // 166400

__device__ float    g_sqn[TN];
__device__ int      g_nn[TN * KNN];
__device__ int      g_choice_is32;
__device__ uint8_t  g_A8[TN * DD];
__device__ int      g_cand_i[TN * 2 * NCAND];

// ============================ helpers =======================================
__device__ __forceinline__ uint32_t smem_u32(const void* p) {
    uint32_t a;
    asm("{ .reg .u64 t; cvta.to.shared.u64 t, %1; cvt.u32.u64 %0, t; }"
        : "=r"(a) : "l"(p));
    return a;
}
__device__ __forceinline__ void cp16(uint32_t dst, const void* src) {
    asm volatile("cp.async.cg.shared.global [%0], [%1], 16;"
                 :: "r"(dst), "l"(src) : "memory");
}
__device__ __forceinline__ void cp_commit() {
    asm volatile("cp.async.commit_group;" ::: "memory");
}
__device__ __forceinline__ void cp_wait0() {
    asm volatile("cp.async.wait_group 0;" ::: "memory");
}
__device__ __forceinline__ void ldsm4(uint32_t* r, uint32_t a) {
    asm volatile("ldmatrix.sync.aligned.m8n8.x4.shared.b16 {%0,%1,%2,%3}, [%4];"
                 : "=r"(r[0]), "=r"(r[1]), "=r"(r[2]), "=r"(r[3]) : "r"(a));
}
__device__ __forceinline__ void qmma(float* c, const uint32_t* a,
                                     uint32_t b0, uint32_t b1) {
    asm volatile("mma.sync.aligned.m16n8k32.row.col.f32.e4m3.e4m3.f32 "
                 "{%0,%1,%2,%3}, {%4,%5,%6,%7}, {%8,%9}, {%0,%1,%2,%3};"
                 : "+f"(c[0]), "+f"(c[1]), "+f"(c[2]), "+f"(c[3])
                 : "r"(a[0]), "r"(a[1]), "r"(a[2]), "r"(a[3]),
                   "r"(b0), "r"(b1));
}
__device__ __forceinline__ uint32_t pack_e4m3x2(float hi, float lo) {
    uint32_t h;  // cvt packs: first f32 operand -> high byte
    asm("{ .reg .b16 t; cvt.rn.satfinite.e4m3x2.f32 t, %1, %2;"
        "  cvt.u32.u16 %0, t; }" : "=r"(h) : "f"(hi), "f"(lo));
    return h;
}
__device__ __forceinline__ bool kless(float v, int id, float w, int jd) {
    return (v < w) || (v == w && id < jd);
}
template <int NC>
__device__ __forceinline__ void topk_insert(float (&kv)[NC], int (&ki)[NC],
                                            float v, int j) {
    if (kless(v, j, kv[NC - 1], ki[NC - 1])) {
        kv[NC - 1] = v; ki[NC - 1] = j;
#pragma unroll
        for (int p = NC - 1; p > 0; --p) {
            if (kless(kv[p], ki[p], kv[p - 1], ki[p - 1])) {
                float tv = kv[p]; kv[p] = kv[p - 1]; kv[p - 1] = tv;
                int   tj = ki[p]; ki[p] = ki[p - 1]; ki[p - 1] = tj;
            }
        }
    }
}

// ======================= fp32 -> fp8 e4m3 ===================================
__global__ void convert_kernel(const float* __restrict__ A) {
    int idx = blockIdx.x * blockDim.x + threadIdx.x;   // 1M threads
    float4 v = reinterpret_cast<const float4*>(A)[idx];
    uint32_t lo = pack_e4m3x2(v.y, v.x);   // byte0=x, byte1=y
    uint32_t hi = pack_e4m3x2(v.w, v.z);   // byte2=z, byte3=w
    reinterpret_cast<uint32_t*>(g_A8)[idx] = lo | (hi << 16);
}

// ============================ sq norms ======================================
__global__ void sqnorm_kernel(const float* __restrict__ A) {
    if (blockIdx.x == 0 && threadIdx.x == 0) g_choice_is32 = 0;
    int row = blockIdx.x;
    const float4* p = reinterpret_cast<const float4*>(A + (size_t)row * DD);
    float4 v = p[threadIdx.x];
    float s = v.x * v.x + v.y * v.y + v.z * v.z + v.w * v.w;
#pragma unroll
    for (int off = 16; off > 0; off >>= 1) s += __shfl_xor_sync(0xffffffffu, s, off);
    __shared__ float ws[4];
    int lane = threadIdx.x & 31, wid = threadIdx.x >> 5;
    if (lane == 0) ws[wid] = s;
    __syncthreads();
    if (threadIdx.x == 0) g_sqn[row] = ws[0] + ws[1] + ws[2] + ws[3];
}

// ===================== int32-vs-int64 detection =============================
__global__ void detect_kernel(const unsigned int* __restrict__ w) {
    int idx = blockIdx.x * blockDim.x + threadIdx.x;
    if (w[2 * idx + 1] != 0u) atomicOr(&g_choice_is32, 1);
}

// ================== tensor-core (fp8 qmma) kNN ==============================
// grid = 128 (64 row-blocks x 2 j-halves), 512 threads (16 warps, 4x4 grid).
// A tile (128x512 e4m3, 64 KB) persistent in smem; B streamed in 128-k
// chunks (16 KB), double-buffered, distance-1 prefetch. Warp tile 32x32.
__global__ __launch_bounds__(512, 1) void knn_mma_kernel() {
    extern __shared__ __align__(16) char smc[];
    const uint32_t sb = smem_u32(smc);
    const int tid  = threadIdx.x;
    const int lane = tid & 31;
    const int wid  = tid >> 5;
    const int wm   = wid >> 2;      // 0..3 -> rows wm*32
    const int wn   = wid & 3;       // 0..3 -> cols wn*32
    const int ib   = blockIdx.x >> 1;
    const int half = blockIdx.x & 1;
    const int brow = ib * KM;
    const int jbase = half * JHALF;

    const int lrow = lane & 15;
    const int lcol = lane >> 4;

    // swizzled 16B offsets within a 128B block for the 4 k32-steps
    uint32_t kof4[4];
#pragma unroll
    for (int i = 0; i < 4; ++i)
        kof4[i] = (uint32_t)(((2 * i + lcol) ^ (lrow & 7)) * 16);
    const uint32_t aro = (uint32_t)((wm * 32 + lrow) * 512);   // A rows: 512 B
    const uint32_t bro = (uint32_t)((wn * 32 + lrow) * 128);   // B rows: 128 B

    float kv[NCAND]; int ki[NCAND];
#pragma unroll
    for (int s = 0; s < NCAND; ++s) { kv[s] = 3.4e38f; ki[s] = 0x7fffffff; }

    uint32_t aF[2][4], bF[2][4];

    // ---- persistent A tile: 128 rows x 32 quads, 8 cp16/thread ----
#pragma unroll
    for (int i = 0; i < 8; ++i) {
        const int f = i * 512 + tid;
        const int r = f >> 5, qq = f & 31;
        const uint32_t d = sb + (uint32_t)(r * 512 + (qq >> 3) * 128 +
                                           ((qq & 7) ^ (r & 7)) * 16);
        cp16(d, g_A8 + (size_t)(brow + r) * DD + qq * 16);
    }
    cp_commit();

#define LOAD_B(G) do {                                                      \
    const int _g = (G);                                                     \
    const uint32_t stg = sb + OFF_B + (uint32_t)(_g & 1) * B_T_B;           \
    const int _kt = (_g & 3) * KCHB;                                        \
    const int _jb = jbase + (_g >> 2) * KNT;                                \
    _Pragma("unroll")                                                       \
    for (int i = 0; i < 2; ++i) {                                           \
        const int f = tid + i * 512;                                        \
        const int r = f >> 3, q = f & 7;                                    \
        const uint32_t dofs = (uint32_t)(r * 128 + ((q ^ (r & 7)) * 16));   \
        cp16(stg + dofs, g_A8 + (size_t)(_jb + r) * DD + _kt + q * 16);     \
    }                                                                       \
    cp_commit();                                                            \
} while (0)

// chunk c covers A byte-block c (128 B); step S = k32 index within chunk
#define LOAD_FRAGS(S) do {                                                  \
    const uint32_t ad = sb + aro + (uint32_t)(c * 128) + kof4[S];           \
    ldsm4(aF[0], ad);  ldsm4(aF[1], ad + 16 * 512);                         \
    const uint32_t bd = bbase + bro + kof4[S];                              \
    ldsm4(bF[0], bd);  ldsm4(bF[1], bd + 16 * 128);                         \
} while (0)

#define MMA_STEP() do {                                                     \
    _Pragma("unroll")                                                       \
    for (int mt = 0; mt < 2; ++mt)                                          \
        _Pragma("unroll")                                                   \
        for (int np = 0; np < 2; ++np)                                      \
            _Pragma("unroll")                                               \
            for (int sel = 0; sel < 2; ++sel)                               \
                qmma(acc[mt][np * 2 + sel], aF[mt],                         \
                     bF[np][sel], bF[np][sel + 2]);                         \
} while (0)

    // prologue: B chunk 0 (A group + B0 retire at the first wait0)
    LOAD_B(0);

    for (int t = 0; t < NTILES; ++t) {
        const int jb = jbase + t * KNT;

        float acc[2][4][4];
#pragma unroll
        for (int a = 0; a < 2; ++a)
#pragma unroll
            for (int b = 0; b < 4; ++b)
#pragma unroll
                for (int c = 0; c < 4; ++c) acc[a][b][c] = 0.0f;

        for (int c = 0; c < NCH; ++c) {
            const int g = t * NCH + c;
            cp_wait0();              // B(g) landed
            __syncthreads();         // all warps done reading stage (g-1)&1
            if (g + 1 < NCHT) LOAD_B(g + 1);   // writes stage (g+1)&1 != g&1

            const uint32_t bbase = sb + OFF_B + (uint32_t)(g & 1) * B_T_B;
            LOAD_FRAGS(0); MMA_STEP();
            LOAD_FRAGS(1); MMA_STEP();
            LOAD_FRAGS(2); MMA_STEP();
            LOAD_FRAGS(3); MMA_STEP();
        }

        // ---- stage dot values + sq[j] to smem ----
        if (tid < 128)
            *(float*)(smc + OFF_SQS + tid * 4) = g_sqn[jb + tid];
        {
            float* Dst = (float*)(smc + OFF_D);
            const int m0 = wm * 32 + (lane >> 2);
            const int n0 = wn * 32 + (lane & 3) * 2;
#pragma unroll
            for (int mt = 0; mt < 2; ++mt)
#pragma unroll
                for (int nt = 0; nt < 4; ++nt) {
                    *(float2*)(Dst + (m0 + mt * 16    ) * DSTRIDE + n0 + nt * 8) =
                        make_float2(acc[mt][nt][0], acc[mt][nt][1]);
                    *(float2*)(Dst + (m0 + mt * 16 + 8) * DSTRIDE + n0 + nt * 8) =
                        make_float2(acc[mt][nt][2], acc[mt][nt][3]);
                }
        }
        __syncthreads();

        // ---- selection: 4 threads per row, 32 cols each, register lists ----
        {
            const int row = tid & 127, qtr = tid >> 7;
            const int grow = brow + row;
            const float4* Dp  = (const float4*)((const float*)(smc + OFF_D) +
                                                row * DSTRIDE + qtr * 32);
            const float4* sqp = (const float4*)((const float*)(smc + OFF_SQS) +
                                                qtr * 32);
            const int j0 = jb + qtr * 32;
#pragma unroll
            for (int n4 = 0; n4 < 8; ++n4) {
                float4 d4 = Dp[n4];
                float4 s4 = sqp[n4];
                const int j = j0 + n4 * 4;
                float v0 = s4.x - 2.0f * d4.x;
                float v1 = s4.y - 2.0f * d4.y;
                float v2 = s4.z - 2.0f * d4.z;
                float v3 = s4.w - 2.0f * d4.w;
                if (j + 0 != grow) topk_insert<NCAND>(kv, ki, v0, j + 0);
                if (j + 1 != grow) topk_insert<NCAND>(kv, ki, v1, j + 1);
                if (j + 2 != grow) topk_insert<NCAND>(kv, ki, v2, j + 2);
                if (j + 3 != grow) topk_insert<NCAND>(kv, ki, v3, j + 3);
            }
        }
        // next D write happens after the next tile's chunk barriers -> safe
    }

    // ---- merge the 4 per-row lists through smem, write candidates ----------
    __syncthreads();
    {
        float* mv = (float*)(smc + OFF_D);
        int*   mi = (int*)(smc + OFF_D) + 512 * NCAND;
#pragma unroll
        for (int s = 0; s < NCAND; ++s) {
            mv[tid * NCAND + s] = kv[s];
            mi[tid * NCAND + s] = ki[s];
        }
    }
    __syncthreads();
    if (tid < 128) {
        float* mv = (float*)(smc + OFF_D);
        int*   mi = (int*)(smc + OFF_D) + 512 * NCAND;
#pragma unroll
        for (int o = 1; o < 4; ++o) {
            const int b = (tid + o * 128) * NCAND;
#pragma unroll
            for (int s = 0; s < NCAND; ++s)
                topk_insert<NCAND>(kv, ki, mv[b + s], mi[b + s]);
        }
        const int grow = brow + tid;
        const int base = (grow * 2 + half) * NCAND;
#pragma unroll
        for (int s = 0; s < NCAND; ++s) g_cand_i[base + s] = ki[s];
    }
#undef LOAD_B
#undef LOAD_FRAGS
#undef MMA_STEP
}

// ========= exact fp32 rescore of 32 candidates -> top-5 =====================
// 512 threads = 16 warps; warp w rescored candidates w and w+16.
__global__ __launch_bounds__(512, 1) void rescore_kernel(const float* __restrict__ A) {
    const int row = blockIdx.x;
    const int w = threadIdx.x >> 5, lane = threadIdx.x & 31;
    __shared__ float sa[DD];
    __shared__ float sv[2 * NCAND];
    __shared__ int   si[2 * NCAND];
    if (threadIdx.x < DD) sa[threadIdx.x] = A[(size_t)row * DD + threadIdx.x];
    __syncthreads();
#pragma unroll
    for (int rep = 0; rep < 2; ++rep) {
        const int e = w + rep * 16;
        const int j = g_cand_i[row * (2 * NCAND) + e];
        const float* aj = A + (size_t)j * DD;
        float dot = 0.0f;
#pragma unroll
        for (int k = 0; k < 16; ++k) dot += sa[lane + k * 32] * aj[lane + k * 32];
#pragma unroll
        for (int off = 16; off > 0; off >>= 1)
            dot += __shfl_xor_sync(0xffffffffu, dot, off);
        if (lane == 0) { sv[e] = g_sqn[j] - 2.0f * dot; si[e] = j; }
    }
    __syncthreads();
    if (threadIdx.x == 0) {
        float bv[KNN]; int bi[KNN];
#pragma unroll
        for (int s = 0; s < KNN; ++s) { bv[s] = 3.4e38f; bi[s] = 0x7fffffff; }
        for (int e = 0; e < 2 * NCAND; ++e) {
            float v = sv[e]; int id = si[e];
            if (kless(v, id, bv[KNN - 1], bi[KNN - 1])) {
                bv[KNN - 1] = v; bi[KNN - 1] = id;
#pragma unroll
                for (int p = KNN - 1; p > 0; --p) {
                    if (kless(bv[p], bi[p], bv[p - 1], bi[p - 1])) {
                        float fv = bv[p]; bv[p] = bv[p - 1]; bv[p - 1] = fv;
                        int   iv = bi[p]; bi[p] = bi[p - 1]; bi[p - 1] = iv;
                    }
                }
            }
        }
#pragma unroll
        for (int s = 0; s < KNN; ++s) g_nn[row * KNN + s] = bi[s];
    }
}

// ===================== SMOTE interpolation ==================================
__global__ void populate_kernel(const float* __restrict__ A,
                                const float* __restrict__ gaps,
                                const unsigned int* __restrict__ cw,
                                float* __restrict__ out) {
    int o = blockIdx.x;
    int i = o >> 2;
    float g = gaps[o];
    int widx = g_choice_is32 ? o : (o << 1);
    int c  = (int)cw[widx];
    int nb = g_nn[i * KNN + c];
    const float4* ai = reinterpret_cast<const float4*>(A + (size_t)i  * DD);
    const float4* an = reinterpret_cast<const float4*>(A + (size_t)nb * DD);
    float4* op = reinterpret_cast<float4*>(out) + (size_t)o * (DD / 4);
    int t = threadIdx.x;
    float4 a = ai[t], b = an[t];
    float4 r;
    r.x = a.x + g * (b.x - a.x);
    r.y = a.y + g * (b.y - a.y);
    r.z = a.z + g * (b.z - a.z);
    r.w = a.w + g * (b.w - a.w);
    op[t] = r;
}

// ============================================================================
extern "C" void kernel_launch(void* const* d_in, const int* in_sizes, int n_in,
                              void* d_out, int out_size) {
    const float* A         = (const float*)d_in[0];
    const float* gaps      = (const float*)d_in[1];
    const unsigned int* cw = (const unsigned int*)d_in[2];
    float* out             = (float*)d_out;

    cudaFuncSetAttribute(knn_mma_kernel,
                         cudaFuncAttributeMaxDynamicSharedMemorySize, SMEM_TOTAL);

    convert_kernel<<<TN * DD / 4 / 256, 256>>>(A);
    sqnorm_kernel<<<TN, 128>>>(A);
    detect_kernel<<<64, 256>>>(cw);
    knn_mma_kernel<<<128, 512, SMEM_TOTAL>>>();
    rescore_kernel<<<TN, 512>>>(A);
    populate_kernel<<<TN * NPER, 128>>>(A, gaps, cw, out);
}

// round 15
// speedup vs baseline: 1.8373x; 1.8373x over previous
#include <cuda_runtime.h>
#include <cuda_bf16.h>
#include <cstdint>

#define TN    8192
#define DD    512
#define NPER  4
#define KNN   5
#define NCAND 12                     // candidates per row per j-half

#define KM      128                  // rows per CTA (A persistent in smem)
#define KNT     128                  // j cols per tile
#define JHALF   (TN / 2)
#define NTILES  (JHALF / KNT)        // 32
#define KCHB    128                  // k bytes per B chunk (fp8: 128 k elems)
#define NCH     4                    // chunks per tile (4 x 128 k = 512)
#define NCHT    (NTILES * NCH)       // 128 global chunks
#define A_BYTES 65536                // 128 x 512 fp8, swizzled
#define B_T_B   16384                // 128 rows x 128 B
#define OFF_B   65536
#define OFF_D   98304
#define DSTRIDE 132
#define OFF_SQS (OFF_D + KM * DSTRIDE * 4)   // 165888
#define SMEM_TOTAL (OFF_SQS + 512)           // 166400

__device__ float    g_sqn[TN];
__device__ int      g_nn[TN * KNN];
__device__ int      g_choice_is32;
__device__ uint8_t  g_A8[TN * DD];
__device__ int      g_cand_i[TN * 2 * NCAND];

// ============================ helpers =======================================
__device__ __forceinline__ uint32_t smem_u32(const void* p) {
    uint32_t a;
    asm("{ .reg .u64 t; cvta.to.shared.u64 t, %1; cvt.u32.u64 %0, t; }"
        : "=r"(a) : "l"(p));
    return a;
}
__device__ __forceinline__ void cp16(uint32_t dst, const void* src) {
    asm volatile("cp.async.cg.shared.global [%0], [%1], 16;"
                 :: "r"(dst), "l"(src) : "memory");
}
__device__ __forceinline__ void cp_commit() {
    asm volatile("cp.async.commit_group;" ::: "memory");
}
__device__ __forceinline__ void cp_wait0() {
    asm volatile("cp.async.wait_group 0;" ::: "memory");
}
__device__ __forceinline__ void ldsm4(uint32_t* r, uint32_t a) {
    asm volatile("ldmatrix.sync.aligned.m8n8.x4.shared.b16 {%0,%1,%2,%3}, [%4];"
                 : "=r"(r[0]), "=r"(r[1]), "=r"(r[2]), "=r"(r[3]) : "r"(a));
}
__device__ __forceinline__ void qmma(float* c, const uint32_t* a,
                                     uint32_t b0, uint32_t b1) {
    asm volatile("mma.sync.aligned.m16n8k32.row.col.f32.e4m3.e4m3.f32 "
                 "{%0,%1,%2,%3}, {%4,%5,%6,%7}, {%8,%9}, {%0,%1,%2,%3};"
                 : "+f"(c[0]), "+f"(c[1]), "+f"(c[2]), "+f"(c[3])
                 : "r"(a[0]), "r"(a[1]), "r"(a[2]), "r"(a[3]),
                   "r"(b0), "r"(b1));
}
__device__ __forceinline__ uint32_t pack_e4m3x2(float hi, float lo) {
    uint32_t h;  // cvt packs: first f32 operand -> high byte
    asm("{ .reg .b16 t; cvt.rn.satfinite.e4m3x2.f32 t, %1, %2;"
        "  cvt.u32.u16 %0, t; }" : "=r"(h) : "f"(hi), "f"(lo));
    return h;
}
__device__ __forceinline__ bool kless(float v, int id, float w, int jd) {
    return (v < w) || (v == w && id < jd);
}
template <int NC>
__device__ __forceinline__ void topk_insert(float (&kv)[NC], int (&ki)[NC],
                                            float v, int j) {
    if (kless(v, j, kv[NC - 1], ki[NC - 1])) {
        kv[NC - 1] = v; ki[NC - 1] = j;
#pragma unroll
        for (int p = NC - 1; p > 0; --p) {
            if (kless(kv[p], ki[p], kv[p - 1], ki[p - 1])) {
                float tv = kv[p]; kv[p] = kv[p - 1]; kv[p - 1] = tv;
                int   tj = ki[p]; ki[p] = ki[p - 1]; ki[p - 1] = tj;
            }
        }
    }
}

// ======================= fp32 -> fp8 e4m3 ===================================
__global__ void convert_kernel(const float* __restrict__ A) {
    int idx = blockIdx.x * blockDim.x + threadIdx.x;   // 1M threads
    float4 v = reinterpret_cast<const float4*>(A)[idx];
    uint32_t lo = pack_e4m3x2(v.y, v.x);   // byte0=x, byte1=y
    uint32_t hi = pack_e4m3x2(v.w, v.z);   // byte2=z, byte3=w
    reinterpret_cast<uint32_t*>(g_A8)[idx] = lo | (hi << 16);
}

// ============================ sq norms ======================================
__global__ void sqnorm_kernel(const float* __restrict__ A) {
    if (blockIdx.x == 0 && threadIdx.x == 0) g_choice_is32 = 0;
    int row = blockIdx.x;
    const float4* p = reinterpret_cast<const float4*>(A + (size_t)row * DD);
    float4 v = p[threadIdx.x];
    float s = v.x * v.x + v.y * v.y + v.z * v.z + v.w * v.w;
#pragma unroll
    for (int off = 16; off > 0; off >>= 1) s += __shfl_xor_sync(0xffffffffu, s, off);
    __shared__ float ws[4];
    int lane = threadIdx.x & 31, wid = threadIdx.x >> 5;
    if (lane == 0) ws[wid] = s;
    __syncthreads();
    if (threadIdx.x == 0) g_sqn[row] = ws[0] + ws[1] + ws[2] + ws[3];
}

// ===================== int32-vs-int64 detection =============================
__global__ void detect_kernel(const unsigned int* __restrict__ w) {
    int idx = blockIdx.x * blockDim.x + threadIdx.x;
    if (w[2 * idx + 1] != 0u) atomicOr(&g_choice_is32, 1);
}

// ================== tensor-core (fp8 qmma) kNN ==============================
// grid = 128 (64 row-blocks x 2 j-halves), 512 threads (16 warps, 4x4 grid).
// A tile (128x512 e4m3, 64 KB) persistent in smem; B streamed in 128-k
// chunks (16 KB), double-buffered, distance-1 prefetch. Warp tile 32x32,
// fragment double-buffering across the 4 k32 steps of each chunk.
__global__ __launch_bounds__(512, 1) void knn_mma_kernel() {
    extern __shared__ __align__(16) char smc[];
    const uint32_t sb = smem_u32(smc);
    const int tid  = threadIdx.x;
    const int lane = tid & 31;
    const int wid  = tid >> 5;
    const int wm   = wid >> 2;      // 0..3 -> rows wm*32
    const int wn   = wid & 3;       // 0..3 -> cols wn*32
    const int ib   = blockIdx.x >> 1;
    const int half = blockIdx.x & 1;
    const int brow = ib * KM;
    const int jbase = half * JHALF;

    const int lrow = lane & 15;
    const int lcol = lane >> 4;

    // swizzled 16B offsets within a 128B block for the 4 k32-steps
    uint32_t kof4[4];
#pragma unroll
    for (int i = 0; i < 4; ++i)
        kof4[i] = (uint32_t)(((2 * i + lcol) ^ (lrow & 7)) * 16);
    const uint32_t aro = (uint32_t)((wm * 32 + lrow) * 512);   // A rows: 512 B
    const uint32_t bro = (uint32_t)((wn * 32 + lrow) * 128);   // B rows: 128 B

    float kv[NCAND]; int ki[NCAND];
#pragma unroll
    for (int s = 0; s < NCAND; ++s) { kv[s] = 3.4e38f; ki[s] = 0x7fffffff; }

    uint32_t aF0[2][4], bF0[2][4];
    uint32_t aF1[2][4], bF1[2][4];

    // ---- persistent A tile: 128 rows x 32 quads, 8 cp16/thread ----
#pragma unroll
    for (int i = 0; i < 8; ++i) {
        const int f = i * 512 + tid;
        const int r = f >> 5, qq = f & 31;
        const uint32_t d = sb + (uint32_t)(r * 512 + (qq >> 3) * 128 +
                                           ((qq & 7) ^ (r & 7)) * 16);
        cp16(d, g_A8 + (size_t)(brow + r) * DD + qq * 16);
    }
    cp_commit();

#define LOAD_B(G) do {                                                      \
    const int _g = (G);                                                     \
    const uint32_t stg = sb + OFF_B + (uint32_t)(_g & 1) * B_T_B;           \
    const int _kt = (_g & 3) * KCHB;                                        \
    const int _jb = jbase + (_g >> 2) * KNT;                                \
    _Pragma("unroll")                                                       \
    for (int i = 0; i < 2; ++i) {                                           \
        const int f = tid + i * 512;                                        \
        const int r = f >> 3, q = f & 7;                                    \
        const uint32_t dofs = (uint32_t)(r * 128 + ((q ^ (r & 7)) * 16));   \
        cp16(stg + dofs, g_A8 + (size_t)(_jb + r) * DD + _kt + q * 16);     \
    }                                                                       \
    cp_commit();                                                            \
} while (0)

// chunk c covers A byte-block c (128 B); step S = k32 index within chunk
#define LOAD_FRAGS(B, S) do {                                               \
    const uint32_t ad = sb + aro + (uint32_t)(c * 128) + kof4[S];           \
    ldsm4(aF##B[0], ad);  ldsm4(aF##B[1], ad + 16 * 512);                   \
    const uint32_t bd = bbase + bro + kof4[S];                              \
    ldsm4(bF##B[0], bd);  ldsm4(bF##B[1], bd + 16 * 128);                   \
} while (0)

#define MMA_STEP(B) do {                                                    \
    _Pragma("unroll")                                                       \
    for (int mt = 0; mt < 2; ++mt)                                          \
        _Pragma("unroll")                                                   \
        for (int np = 0; np < 2; ++np)                                      \
            _Pragma("unroll")                                               \
            for (int sel = 0; sel < 2; ++sel)                               \
                qmma(acc[mt][np * 2 + sel], aF##B[mt],                      \
                     bF##B[np][sel], bF##B[np][sel + 2]);                   \
} while (0)

    // prologue: B chunk 0 (A group + B0 retire at the first wait0)
    LOAD_B(0);

    for (int t = 0; t < NTILES; ++t) {
        const int jb = jbase + t * KNT;

        float acc[2][4][4];
#pragma unroll
        for (int a = 0; a < 2; ++a)
#pragma unroll
            for (int b = 0; b < 4; ++b)
#pragma unroll
                for (int c = 0; c < 4; ++c) acc[a][b][c] = 0.0f;

        for (int c = 0; c < NCH; ++c) {
            const int g = t * NCH + c;
            cp_wait0();              // B(g) landed (issued one chunk earlier)
            __syncthreads();         // all warps done reading stage (g-1)&1
            if (g + 1 < NCHT) LOAD_B(g + 1);   // writes stage (g+1)&1 != g&1

            const uint32_t bbase = sb + OFF_B + (uint32_t)(g & 1) * B_T_B;
            LOAD_FRAGS(0, 0);
            LOAD_FRAGS(1, 1);
            MMA_STEP(0);
            LOAD_FRAGS(0, 2);
            MMA_STEP(1);
            LOAD_FRAGS(1, 3);
            MMA_STEP(0);
            MMA_STEP(1);
        }

        // ---- stage dot values + sq[j] to smem ----
        if (tid < 128)
            *(float*)(smc + OFF_SQS + tid * 4) = g_sqn[jb + tid];
        {
            float* Dst = (float*)(smc + OFF_D);
            const int m0 = wm * 32 + (lane >> 2);
            const int n0 = wn * 32 + (lane & 3) * 2;
#pragma unroll
            for (int mt = 0; mt < 2; ++mt)
#pragma unroll
                for (int nt = 0; nt < 4; ++nt) {
                    *(float2*)(Dst + (m0 + mt * 16    ) * DSTRIDE + n0 + nt * 8) =
                        make_float2(acc[mt][nt][0], acc[mt][nt][1]);
                    *(float2*)(Dst + (m0 + mt * 16 + 8) * DSTRIDE + n0 + nt * 8) =
                        make_float2(acc[mt][nt][2], acc[mt][nt][3]);
                }
        }
        __syncthreads();

        // ---- selection: 4 threads per row, 32 cols each, register lists ----
        {
            const int row = tid & 127, qtr = tid >> 7;
            const int grow = brow + row;
            const float4* Dp  = (const float4*)((const float*)(smc + OFF_D) +
                                                row * DSTRIDE + qtr * 32);
            const float4* sqp = (const float4*)((const float*)(smc + OFF_SQS) +
                                                qtr * 32);
            const int j0 = jb + qtr * 32;
#pragma unroll
            for (int n4 = 0; n4 < 8; ++n4) {
                float4 d4 = Dp[n4];
                float4 s4 = sqp[n4];
                const int j = j0 + n4 * 4;
                float v0 = s4.x - 2.0f * d4.x;
                float v1 = s4.y - 2.0f * d4.y;
                float v2 = s4.z - 2.0f * d4.z;
                float v3 = s4.w - 2.0f * d4.w;
                if (j + 0 != grow) topk_insert<NCAND>(kv, ki, v0, j + 0);
                if (j + 1 != grow) topk_insert<NCAND>(kv, ki, v1, j + 1);
                if (j + 2 != grow) topk_insert<NCAND>(kv, ki, v2, j + 2);
                if (j + 3 != grow) topk_insert<NCAND>(kv, ki, v3, j + 3);
            }
        }
        // next D write happens after the next tile's chunk barriers -> safe
    }

    // ---- merge the 4 per-row lists through smem, write candidates ----------
    __syncthreads();
    {
        float* mv = (float*)(smc + OFF_D);
        int*   mi = (int*)(smc + OFF_D) + 512 * NCAND;
#pragma unroll
        for (int s = 0; s < NCAND; ++s) {
            mv[tid * NCAND + s] = kv[s];
            mi[tid * NCAND + s] = ki[s];
        }
    }
    __syncthreads();
    if (tid < 128) {
        float* mv = (float*)(smc + OFF_D);
        int*   mi = (int*)(smc + OFF_D) + 512 * NCAND;
#pragma unroll
        for (int o = 1; o < 4; ++o) {
            const int b = (tid + o * 128) * NCAND;
#pragma unroll
            for (int s = 0; s < NCAND; ++s)
                topk_insert<NCAND>(kv, ki, mv[b + s], mi[b + s]);
        }
        const int grow = brow + tid;
        const int base = (grow * 2 + half) * NCAND;
#pragma unroll
        for (int s = 0; s < NCAND; ++s) g_cand_i[base + s] = ki[s];
    }
#undef LOAD_B
#undef LOAD_FRAGS
#undef MMA_STEP
}

// ========= exact fp32 rescore of 24 candidates -> top-5 =====================
__global__ __launch_bounds__(768, 1) void rescore_kernel(const float* __restrict__ A) {
    const int row = blockIdx.x;
    const int w = threadIdx.x >> 5, lane = threadIdx.x & 31;  // 24 warps
    __shared__ float sa[DD];
    __shared__ float sv[2 * NCAND];
    __shared__ int   si[2 * NCAND];
    if (threadIdx.x < DD) sa[threadIdx.x] = A[(size_t)row * DD + threadIdx.x];
    __syncthreads();
    const int j = g_cand_i[row * (2 * NCAND) + w];
    const float* aj = A + (size_t)j * DD;
    float dot = 0.0f;
#pragma unroll
    for (int k = 0; k < 16; ++k) dot += sa[lane + k * 32] * aj[lane + k * 32];
#pragma unroll
    for (int off = 16; off > 0; off >>= 1) dot += __shfl_xor_sync(0xffffffffu, dot, off);
    if (lane == 0) { sv[w] = g_sqn[j] - 2.0f * dot; si[w] = j; }
    __syncthreads();
    if (threadIdx.x == 0) {
        float bv[KNN]; int bi[KNN];
#pragma unroll
        for (int s = 0; s < KNN; ++s) { bv[s] = 3.4e38f; bi[s] = 0x7fffffff; }
        for (int e = 0; e < 2 * NCAND; ++e) {
            float v = sv[e]; int id = si[e];
            if (kless(v, id, bv[KNN - 1], bi[KNN - 1])) {
                bv[KNN - 1] = v; bi[KNN - 1] = id;
#pragma unroll
                for (int p = KNN - 1; p > 0; --p) {
                    if (kless(bv[p], bi[p], bv[p - 1], bi[p - 1])) {
                        float fv = bv[p]; bv[p] = bv[p - 1]; bv[p - 1] = fv;
                        int   iv = bi[p]; bi[p] = bi[p - 1]; bi[p - 1] = iv;
                    }
                }
            }
        }
#pragma unroll
        for (int s = 0; s < KNN; ++s) g_nn[row * KNN + s] = bi[s];
    }
}

// ===================== SMOTE interpolation ==================================
__global__ void populate_kernel(const float* __restrict__ A,
                                const float* __restrict__ gaps,
                                const unsigned int* __restrict__ cw,
                                float* __restrict__ out) {
    int o = blockIdx.x;
    int i = o >> 2;
    float g = gaps[o];
    int widx = g_choice_is32 ? o : (o << 1);
    int c  = (int)cw[widx];
    int nb = g_nn[i * KNN + c];
    const float4* ai = reinterpret_cast<const float4*>(A + (size_t)i  * DD);
    const float4* an = reinterpret_cast<const float4*>(A + (size_t)nb * DD);
    float4* op = reinterpret_cast<float4*>(out) + (size_t)o * (DD / 4);
    int t = threadIdx.x;
    float4 a = ai[t], b = an[t];
    float4 r;
    r.x = a.x + g * (b.x - a.x);
    r.y = a.y + g * (b.y - a.y);
    r.z = a.z + g * (b.z - a.z);
    r.w = a.w + g * (b.w - a.w);
    op[t] = r;
}

// ============================================================================
extern "C" void kernel_launch(void* const* d_in, const int* in_sizes, int n_in,
                              void* d_out, int out_size) {
    const float* A         = (const float*)d_in[0];
    const float* gaps      = (const float*)d_in[1];
    const unsigned int* cw = (const unsigned int*)d_in[2];
    float* out             = (float*)d_out;

    cudaFuncSetAttribute(knn_mma_kernel,
                         cudaFuncAttributeMaxDynamicSharedMemorySize, SMEM_TOTAL);

    convert_kernel<<<TN * DD / 4 / 256, 256>>>(A);
    sqnorm_kernel<<<TN, 128>>>(A);
    detect_kernel<<<64, 256>>>(cw);
    knn_mma_kernel<<<128, 512, SMEM_TOTAL>>>();
    rescore_kernel<<<TN, 768>>>(A);
    populate_kernel<<<TN * NPER, 128>>>(A, gaps, cw, out);
}

// round 16
// speedup vs baseline: 3.2983x; 1.7952x over previous
#include <cuda_runtime.h>
#include <cuda_bf16.h>
#include <cstdint>

#define TN    8192
#define DD    512
#define NPER  4
#define KNN   5
#define NCAND 8                      // candidates per row per j-half

#define KM      128                  // rows per CTA (A persistent in smem)
#define KNT     128                  // j cols per tile
#define JHALF   (TN / 2)
#define NTILES  (JHALF / KNT)        // 32
#define KCHB    128                  // k bytes per B chunk (fp8: 128 k elems)
#define NCH     4                    // chunks per tile (4 x 128 k = 512)
#define NCHT    (NTILES * NCH)       // 128 global chunks
#define A_BYTES 65536                // 128 x 512 fp8, swizzled
#define B_T_B   16384                // 128 rows x 128 B
#define OFF_B   65536
#define OFF_D   98304
#define DSTRIDE 132
#define OFF_SQS (OFF_D + KM * DSTRIDE * 4)   // 165888
#define SMEM_TOTAL (OFF_SQS + 512)           // 166400

__device__ float    g_sqn[TN];
__device__ int      g_nn[TN * KNN];
__device__ int      g_choice_is32;
__device__ uint8_t  g_A8[TN * DD];
__device__ int      g_cand_i[TN * 2 * NCAND];

// ============================ helpers =======================================
__device__ __forceinline__ uint32_t smem_u32(const void* p) {
    uint32_t a;
    asm("{ .reg .u64 t; cvta.to.shared.u64 t, %1; cvt.u32.u64 %0, t; }"
        : "=r"(a) : "l"(p));
    return a;
}
__device__ __forceinline__ void cp16(uint32_t dst, const void* src) {
    asm volatile("cp.async.cg.shared.global [%0], [%1], 16;"
                 :: "r"(dst), "l"(src) : "memory");
}
__device__ __forceinline__ void cp_commit() {
    asm volatile("cp.async.commit_group;" ::: "memory");
}
__device__ __forceinline__ void cp_wait0() {
    asm volatile("cp.async.wait_group 0;" ::: "memory");
}
__device__ __forceinline__ void ldsm4(uint32_t* r, uint32_t a) {
    asm volatile("ldmatrix.sync.aligned.m8n8.x4.shared.b16 {%0,%1,%2,%3}, [%4];"
                 : "=r"(r[0]), "=r"(r[1]), "=r"(r[2]), "=r"(r[3]) : "r"(a));
}
__device__ __forceinline__ void qmma(float* c, const uint32_t* a,
                                     uint32_t b0, uint32_t b1) {
    asm volatile("mma.sync.aligned.m16n8k32.row.col.f32.e4m3.e4m3.f32 "
                 "{%0,%1,%2,%3}, {%4,%5,%6,%7}, {%8,%9}, {%0,%1,%2,%3};"
                 : "+f"(c[0]), "+f"(c[1]), "+f"(c[2]), "+f"(c[3])
                 : "r"(a[0]), "r"(a[1]), "r"(a[2]), "r"(a[3]),
                   "r"(b0), "r"(b1));
}
__device__ __forceinline__ uint32_t pack_e4m3x2(float hi, float lo) {
    uint32_t h;  // cvt packs: first f32 operand -> high byte
    asm("{ .reg .b16 t; cvt.rn.satfinite.e4m3x2.f32 t, %1, %2;"
        "  cvt.u32.u16 %0, t; }" : "=r"(h) : "f"(hi), "f"(lo));
    return h;
}
__device__ __forceinline__ bool kless(float v, int id, float w, int jd) {
    return (v < w) || (v == w && id < jd);
}
template <int NC>
__device__ __forceinline__ void topk_insert(float (&kv)[NC], int (&ki)[NC],
                                            float v, int j) {
    if (kless(v, j, kv[NC - 1], ki[NC - 1])) {
        kv[NC - 1] = v; ki[NC - 1] = j;
#pragma unroll
        for (int p = NC - 1; p > 0; --p) {
            if (kless(kv[p], ki[p], kv[p - 1], ki[p - 1])) {
                float tv = kv[p]; kv[p] = kv[p - 1]; kv[p - 1] = tv;
                int   tj = ki[p]; ki[p] = ki[p - 1]; ki[p - 1] = tj;
            }
        }
    }
}

// ======================= fp32 -> fp8 e4m3 ===================================
__global__ void convert_kernel(const float* __restrict__ A) {
    int idx = blockIdx.x * blockDim.x + threadIdx.x;   // 1M threads
    float4 v = reinterpret_cast<const float4*>(A)[idx];
    uint32_t lo = pack_e4m3x2(v.y, v.x);   // byte0=x, byte1=y
    uint32_t hi = pack_e4m3x2(v.w, v.z);   // byte2=z, byte3=w
    reinterpret_cast<uint32_t*>(g_A8)[idx] = lo | (hi << 16);
}

// ============================ sq norms ======================================
__global__ void sqnorm_kernel(const float* __restrict__ A) {
    if (blockIdx.x == 0 && threadIdx.x == 0) g_choice_is32 = 0;
    int row = blockIdx.x;
    const float4* p = reinterpret_cast<const float4*>(A + (size_t)row * DD);
    float4 v = p[threadIdx.x];
    float s = v.x * v.x + v.y * v.y + v.z * v.z + v.w * v.w;
#pragma unroll
    for (int off = 16; off > 0; off >>= 1) s += __shfl_xor_sync(0xffffffffu, s, off);
    __shared__ float ws[4];
    int lane = threadIdx.x & 31, wid = threadIdx.x >> 5;
    if (lane == 0) ws[wid] = s;
    __syncthreads();
    if (threadIdx.x == 0) g_sqn[row] = ws[0] + ws[1] + ws[2] + ws[3];
}

// ===================== int32-vs-int64 detection =============================
__global__ void detect_kernel(const unsigned int* __restrict__ w) {
    int idx = blockIdx.x * blockDim.x + threadIdx.x;
    if (w[2 * idx + 1] != 0u) atomicOr(&g_choice_is32, 1);
}

// ================== tensor-core (fp8 qmma) kNN ==============================
// grid = 128 (64 row-blocks x 2 j-halves), 512 threads (16 warps, 4x4 grid).
// A tile (128x512 e4m3, 64 KB) persistent in smem; B streamed in 128-k
// chunks (16 KB), double-buffered, distance-1 prefetch. Warp tile 32x32,
// fragment double-buffering; register top-8 lists.
__global__ __launch_bounds__(512, 1) void knn_mma_kernel() {
    extern __shared__ __align__(16) char smc[];
    const uint32_t sb = smem_u32(smc);
    const int tid  = threadIdx.x;
    const int lane = tid & 31;
    const int wid  = tid >> 5;
    const int wm   = wid >> 2;      // 0..3 -> rows wm*32
    const int wn   = wid & 3;       // 0..3 -> cols wn*32
    const int ib   = blockIdx.x >> 1;
    const int half = blockIdx.x & 1;
    const int brow = ib * KM;
    const int jbase = half * JHALF;

    const int lrow = lane & 15;
    const int lcol = lane >> 4;

    // swizzled 16B offsets within a 128B block for the 4 k32-steps
    uint32_t kof4[4];
#pragma unroll
    for (int i = 0; i < 4; ++i)
        kof4[i] = (uint32_t)(((2 * i + lcol) ^ (lrow & 7)) * 16);
    const uint32_t aro = (uint32_t)((wm * 32 + lrow) * 512);   // A rows: 512 B
    const uint32_t bro = (uint32_t)((wn * 32 + lrow) * 128);   // B rows: 128 B

    float kv[NCAND]; int ki[NCAND];
#pragma unroll
    for (int s = 0; s < NCAND; ++s) { kv[s] = 3.4e38f; ki[s] = 0x7fffffff; }

    uint32_t aF0[2][4], bF0[2][4];
    uint32_t aF1[2][4], bF1[2][4];

    // ---- persistent A tile: 128 rows x 32 quads, 8 cp16/thread ----
#pragma unroll
    for (int i = 0; i < 8; ++i) {
        const int f = i * 512 + tid;
        const int r = f >> 5, qq = f & 31;
        const uint32_t d = sb + (uint32_t)(r * 512 + (qq >> 3) * 128 +
                                           ((qq & 7) ^ (r & 7)) * 16);
        cp16(d, g_A8 + (size_t)(brow + r) * DD + qq * 16);
    }
    cp_commit();

#define LOAD_B(G) do {                                                      \
    const int _g = (G);                                                     \
    const uint32_t stg = sb + OFF_B + (uint32_t)(_g & 1) * B_T_B;           \
    const int _kt = (_g & 3) * KCHB;                                        \
    const int _jb = jbase + (_g >> 2) * KNT;                                \
    _Pragma("unroll")                                                       \
    for (int i = 0; i < 2; ++i) {                                           \
        const int f = tid + i * 512;                                        \
        const int r = f >> 3, q = f & 7;                                    \
        const uint32_t dofs = (uint32_t)(r * 128 + ((q ^ (r & 7)) * 16));   \
        cp16(stg + dofs, g_A8 + (size_t)(_jb + r) * DD + _kt + q * 16);     \
    }                                                                       \
    cp_commit();                                                            \
} while (0)

// chunk c covers A byte-block c (128 B); step S = k32 index within chunk
#define LOAD_FRAGS(B, S) do {                                               \
    const uint32_t ad = sb + aro + (uint32_t)(c * 128) + kof4[S];           \
    ldsm4(aF##B[0], ad);  ldsm4(aF##B[1], ad + 16 * 512);                   \
    const uint32_t bd = bbase + bro + kof4[S];                              \
    ldsm4(bF##B[0], bd);  ldsm4(bF##B[1], bd + 16 * 128);                   \
} while (0)

#define MMA_STEP(B) do {                                                    \
    _Pragma("unroll")                                                       \
    for (int mt = 0; mt < 2; ++mt)                                          \
        _Pragma("unroll")                                                   \
        for (int np = 0; np < 2; ++np)                                      \
            _Pragma("unroll")                                               \
            for (int sel = 0; sel < 2; ++sel)                               \
                qmma(acc[mt][np * 2 + sel], aF##B[mt],                      \
                     bF##B[np][sel], bF##B[np][sel + 2]);                   \
} while (0)

    // prologue: B chunk 0 (A group + B0 retire at the first wait0)
    LOAD_B(0);

    for (int t = 0; t < NTILES; ++t) {
        const int jb = jbase + t * KNT;

        float acc[2][4][4];
#pragma unroll
        for (int a = 0; a < 2; ++a)
#pragma unroll
            for (int b = 0; b < 4; ++b)
#pragma unroll
                for (int c = 0; c < 4; ++c) acc[a][b][c] = 0.0f;

        for (int c = 0; c < NCH; ++c) {
            const int g = t * NCH + c;
            cp_wait0();              // B(g) landed (issued one chunk earlier)
            __syncthreads();         // all warps done reading stage (g-1)&1
            if (g + 1 < NCHT) LOAD_B(g + 1);   // writes stage (g+1)&1 != g&1

            const uint32_t bbase = sb + OFF_B + (uint32_t)(g & 1) * B_T_B;
            LOAD_FRAGS(0, 0);
            LOAD_FRAGS(1, 1);
            MMA_STEP(0);
            LOAD_FRAGS(0, 2);
            MMA_STEP(1);
            LOAD_FRAGS(1, 3);
            MMA_STEP(0);
            MMA_STEP(1);
        }

        // ---- stage dot values + sq[j] to smem ----
        if (tid < 128)
            *(float*)(smc + OFF_SQS + tid * 4) = g_sqn[jb + tid];
        {
            float* Dst = (float*)(smc + OFF_D);
            const int m0 = wm * 32 + (lane >> 2);
            const int n0 = wn * 32 + (lane & 3) * 2;
#pragma unroll
            for (int mt = 0; mt < 2; ++mt)
#pragma unroll
                for (int nt = 0; nt < 4; ++nt) {
                    *(float2*)(Dst + (m0 + mt * 16    ) * DSTRIDE + n0 + nt * 8) =
                        make_float2(acc[mt][nt][0], acc[mt][nt][1]);
                    *(float2*)(Dst + (m0 + mt * 16 + 8) * DSTRIDE + n0 + nt * 8) =
                        make_float2(acc[mt][nt][2], acc[mt][nt][3]);
                }
        }
        __syncthreads();

        // ---- selection: 4 threads per row, 32 cols each, register lists ----
        {
            const int row = tid & 127, qtr = tid >> 7;
            const int grow = brow + row;
            const float4* Dp  = (const float4*)((const float*)(smc + OFF_D) +
                                                row * DSTRIDE + qtr * 32);
            const float4* sqp = (const float4*)((const float*)(smc + OFF_SQS) +
                                                qtr * 32);
            const int j0 = jb + qtr * 32;
#pragma unroll
            for (int n4 = 0; n4 < 8; ++n4) {
                float4 d4 = Dp[n4];
                float4 s4 = sqp[n4];
                const int j = j0 + n4 * 4;
                float v0 = s4.x - 2.0f * d4.x;
                float v1 = s4.y - 2.0f * d4.y;
                float v2 = s4.z - 2.0f * d4.z;
                float v3 = s4.w - 2.0f * d4.w;
                if (j + 0 != grow) topk_insert<NCAND>(kv, ki, v0, j + 0);
                if (j + 1 != grow) topk_insert<NCAND>(kv, ki, v1, j + 1);
                if (j + 2 != grow) topk_insert<NCAND>(kv, ki, v2, j + 2);
                if (j + 3 != grow) topk_insert<NCAND>(kv, ki, v3, j + 3);
            }
        }
        // next D write happens after the next tile's chunk barriers -> safe
    }

    // ---- merge the 4 per-row lists through smem, write candidates ----------
    __syncthreads();
    {
        float* mv = (float*)(smc + OFF_D);
        int*   mi = (int*)(smc + OFF_D) + 512 * NCAND;
#pragma unroll
        for (int s = 0; s < NCAND; ++s) {
            mv[tid * NCAND + s] = kv[s];
            mi[tid * NCAND + s] = ki[s];
        }
    }
    __syncthreads();
    if (tid < 128) {
        float* mv = (float*)(smc + OFF_D);
        int*   mi = (int*)(smc + OFF_D) + 512 * NCAND;
#pragma unroll
        for (int o = 1; o < 4; ++o) {
            const int b = (tid + o * 128) * NCAND;
#pragma unroll
            for (int s = 0; s < NCAND; ++s)
                topk_insert<NCAND>(kv, ki, mv[b + s], mi[b + s]);
        }
        const int grow = brow + tid;
        const int base = (grow * 2 + half) * NCAND;
#pragma unroll
        for (int s = 0; s < NCAND; ++s) g_cand_i[base + s] = ki[s];
    }
#undef LOAD_B
#undef LOAD_FRAGS
#undef MMA_STEP
}

// ========= exact fp32 rescore of 16 candidates -> top-5 =====================
__global__ __launch_bounds__(512, 1) void rescore_kernel(const float* __restrict__ A) {
    const int row = blockIdx.x;
    const int w = threadIdx.x >> 5, lane = threadIdx.x & 31;  // 16 warps
    __shared__ float sa[DD];
    __shared__ float sv[16];
    __shared__ int   si[16];
    if (threadIdx.x < DD) sa[threadIdx.x] = A[(size_t)row * DD + threadIdx.x];
    __syncthreads();
    const int j = g_cand_i[row * 16 + w];
    const float* aj = A + (size_t)j * DD;
    float dot = 0.0f;
#pragma unroll
    for (int k = 0; k < 16; ++k) dot += sa[lane + k * 32] * aj[lane + k * 32];
#pragma unroll
    for (int off = 16; off > 0; off >>= 1) dot += __shfl_xor_sync(0xffffffffu, dot, off);
    if (lane == 0) { sv[w] = g_sqn[j] - 2.0f * dot; si[w] = j; }
    __syncthreads();
    if (threadIdx.x == 0) {
        float bv[KNN]; int bi[KNN];
#pragma unroll
        for (int s = 0; s < KNN; ++s) { bv[s] = 3.4e38f; bi[s] = 0x7fffffff; }
        for (int e = 0; e < 16; ++e) {
            float v = sv[e]; int id = si[e];
            if (kless(v, id, bv[KNN - 1], bi[KNN - 1])) {
                bv[KNN - 1] = v; bi[KNN - 1] = id;
#pragma unroll
                for (int p = KNN - 1; p > 0; --p) {
                    if (kless(bv[p], bi[p], bv[p - 1], bi[p - 1])) {
                        float fv = bv[p]; bv[p] = bv[p - 1]; bv[p - 1] = fv;
                        int   iv = bi[p]; bi[p] = bi[p - 1]; bi[p - 1] = iv;
                    }
                }
            }
        }
#pragma unroll
        for (int s = 0; s < KNN; ++s) g_nn[row * KNN + s] = bi[s];
    }
}

// ===================== SMOTE interpolation ==================================
__global__ void populate_kernel(const float* __restrict__ A,
                                const float* __restrict__ gaps,
                                const unsigned int* __restrict__ cw,
                                float* __restrict__ out) {
    int o = blockIdx.x;
    int i = o >> 2;
    float g = gaps[o];
    int widx = g_choice_is32 ? o : (o << 1);
    int c  = (int)cw[widx];
    int nb = g_nn[i * KNN + c];
    const float4* ai = reinterpret_cast<const float4*>(A + (size_t)i  * DD);
    const float4* an = reinterpret_cast<const float4*>(A + (size_t)nb * DD);
    float4* op = reinterpret_cast<float4*>(out) + (size_t)o * (DD / 4);
    int t = threadIdx.x;
    float4 a = ai[t], b = an[t];
    float4 r;
    r.x = a.x + g * (b.x - a.x);
    r.y = a.y + g * (b.y - a.y);
    r.z = a.z + g * (b.z - a.z);
    r.w = a.w + g * (b.w - a.w);
    op[t] = r;
}

// ============================================================================
extern "C" void kernel_launch(void* const* d_in, const int* in_sizes, int n_in,
                              void* d_out, int out_size) {
    const float* A         = (const float*)d_in[0];
    const float* gaps      = (const float*)d_in[1];
    const unsigned int* cw = (const unsigned int*)d_in[2];
    float* out             = (float*)d_out;

    cudaFuncSetAttribute(knn_mma_kernel,
                         cudaFuncAttributeMaxDynamicSharedMemorySize, SMEM_TOTAL);

    convert_kernel<<<TN * DD / 4 / 256, 256>>>(A);
    sqnorm_kernel<<<TN, 128>>>(A);
    detect_kernel<<<64, 256>>>(cw);
    knn_mma_kernel<<<128, 512, SMEM_TOTAL>>>();
    rescore_kernel<<<TN, 512>>>(A);
    populate_kernel<<<TN * NPER, 128>>>(A, gaps, cw, out);
}

// round 17
// speedup vs baseline: 3.3516x; 1.0162x over previous
#include <cuda_runtime.h>
#include <cuda_bf16.h>
#include <cstdint>

#define TN    8192
#define DD    512
#define NPER  4
#define KNN   5
#define NCAND 8                      // candidates per row per j-half

#define KM      128                  // rows per CTA (A persistent in smem)
#define KNT     128                  // j cols per tile
#define JHALF   (TN / 2)
#define NTILES  (JHALF / KNT)        // 32
#define KCHB    256                  // k bytes per B chunk (fp8: 256 k elems)
#define NCH     2                    // chunks per tile (2 x 256 k = 512)
#define NCHT    (NTILES * NCH)       // 64 global chunks
#define A_BYTES 65536                // 128 x 512 fp8, swizzled
#define B_T_B   32768                // 128 rows x 256 B
#define OFF_B   65536
#define OFF_D   131072
#define DSTRIDE 132
#define OFF_SQS (OFF_D + KM * DSTRIDE * 4)   // 198656
#define SMEM_TOTAL (OFF_SQS + 512)           // 199168

__device__ float    g_sqn[TN];
__device__ int      g_nn[TN * KNN];
__device__ int      g_choice_is32;
__device__ uint8_t  g_A8[TN * DD];
__device__ int      g_cand_i[TN * 2 * NCAND];

// ============================ helpers =======================================
__device__ __forceinline__ uint32_t smem_u32(const void* p) {
    uint32_t a;
    asm("{ .reg .u64 t; cvta.to.shared.u64 t, %1; cvt.u32.u64 %0, t; }"
        : "=r"(a) : "l"(p));
    return a;
}
__device__ __forceinline__ void cp16(uint32_t dst, const void* src) {
    asm volatile("cp.async.cg.shared.global [%0], [%1], 16;"
                 :: "r"(dst), "l"(src) : "memory");
}
__device__ __forceinline__ void cp_commit() {
    asm volatile("cp.async.commit_group;" ::: "memory");
}
__device__ __forceinline__ void cp_wait0() {
    asm volatile("cp.async.wait_group 0;" ::: "memory");
}
__device__ __forceinline__ void ldsm4(uint32_t* r, uint32_t a) {
    asm volatile("ldmatrix.sync.aligned.m8n8.x4.shared.b16 {%0,%1,%2,%3}, [%4];"
                 : "=r"(r[0]), "=r"(r[1]), "=r"(r[2]), "=r"(r[3]) : "r"(a));
}
__device__ __forceinline__ void qmma(float* c, const uint32_t* a,
                                     uint32_t b0, uint32_t b1) {
    asm volatile("mma.sync.aligned.m16n8k32.row.col.f32.e4m3.e4m3.f32 "
                 "{%0,%1,%2,%3}, {%4,%5,%6,%7}, {%8,%9}, {%0,%1,%2,%3};"
                 : "+f"(c[0]), "+f"(c[1]), "+f"(c[2]), "+f"(c[3])
                 : "r"(a[0]), "r"(a[1]), "r"(a[2]), "r"(a[3]),
                   "r"(b0), "r"(b1));
}
__device__ __forceinline__ uint32_t pack_e4m3x2(float hi, float lo) {
    uint32_t h;  // cvt packs: first f32 operand -> high byte
    asm("{ .reg .b16 t; cvt.rn.satfinite.e4m3x2.f32 t, %1, %2;"
        "  cvt.u32.u16 %0, t; }" : "=r"(h) : "f"(hi), "f"(lo));
    return h;
}
__device__ __forceinline__ bool kless(float v, int id, float w, int jd) {
    return (v < w) || (v == w && id < jd);
}
template <int NC>
__device__ __forceinline__ void topk_insert(float (&kv)[NC], int (&ki)[NC],
                                            float v, int j) {
    if (kless(v, j, kv[NC - 1], ki[NC - 1])) {
        kv[NC - 1] = v; ki[NC - 1] = j;
#pragma unroll
        for (int p = NC - 1; p > 0; --p) {
            if (kless(kv[p], ki[p], kv[p - 1], ki[p - 1])) {
                float tv = kv[p]; kv[p] = kv[p - 1]; kv[p - 1] = tv;
                int   tj = ki[p]; ki[p] = ki[p - 1]; ki[p - 1] = tj;
            }
        }
    }
}

// ======================= fp32 -> fp8 e4m3 ===================================
__global__ void convert_kernel(const float* __restrict__ A) {
    int idx = blockIdx.x * blockDim.x + threadIdx.x;   // 1M threads
    float4 v = reinterpret_cast<const float4*>(A)[idx];
    uint32_t lo = pack_e4m3x2(v.y, v.x);   // byte0=x, byte1=y
    uint32_t hi = pack_e4m3x2(v.w, v.z);   // byte2=z, byte3=w
    reinterpret_cast<uint32_t*>(g_A8)[idx] = lo | (hi << 16);
}

// ============================ sq norms ======================================
__global__ void sqnorm_kernel(const float* __restrict__ A) {
    if (blockIdx.x == 0 && threadIdx.x == 0) g_choice_is32 = 0;
    int row = blockIdx.x;
    const float4* p = reinterpret_cast<const float4*>(A + (size_t)row * DD);
    float4 v = p[threadIdx.x];
    float s = v.x * v.x + v.y * v.y + v.z * v.z + v.w * v.w;
#pragma unroll
    for (int off = 16; off > 0; off >>= 1) s += __shfl_xor_sync(0xffffffffu, s, off);
    __shared__ float ws[4];
    int lane = threadIdx.x & 31, wid = threadIdx.x >> 5;
    if (lane == 0) ws[wid] = s;
    __syncthreads();
    if (threadIdx.x == 0) g_sqn[row] = ws[0] + ws[1] + ws[2] + ws[3];
}

// ===================== int32-vs-int64 detection =============================
__global__ void detect_kernel(const unsigned int* __restrict__ w) {
    int idx = blockIdx.x * blockDim.x + threadIdx.x;
    if (w[2 * idx + 1] != 0u) atomicOr(&g_choice_is32, 1);
}

// ================== tensor-core (fp8 qmma) kNN ==============================
// grid = 128 (64 row-blocks x 2 j-halves), 512 threads (16 warps, 4x4 grid).
// A tile (128x512 e4m3, 64 KB) persistent in smem; B streamed in 256-k
// chunks (32 KB), double-buffered, distance-1 prefetch. Warp tile 32x32,
// fragment double-buffering over 8 k32 steps per chunk; register top-8.
__global__ __launch_bounds__(512, 1) void knn_mma_kernel() {
    extern __shared__ __align__(16) char smc[];
    const uint32_t sb = smem_u32(smc);
    const int tid  = threadIdx.x;
    const int lane = tid & 31;
    const int wid  = tid >> 5;
    const int wm   = wid >> 2;      // 0..3 -> rows wm*32
    const int wn   = wid & 3;       // 0..3 -> cols wn*32
    const int ib   = blockIdx.x >> 1;
    const int half = blockIdx.x & 1;
    const int brow = ib * KM;
    const int jbase = half * JHALF;

    const int lrow = lane & 15;
    const int lcol = lane >> 4;

    // swizzled 16B offsets within a 128B block for k32-steps (mod 4)
    uint32_t kof4[4];
#pragma unroll
    for (int i = 0; i < 4; ++i)
        kof4[i] = (uint32_t)(((2 * i + lcol) ^ (lrow & 7)) * 16);
    const uint32_t aro = (uint32_t)((wm * 32 + lrow) * 512);   // A rows: 512 B
    const uint32_t bro = (uint32_t)((wn * 32 + lrow) * 256);   // B rows: 256 B

    float kv[NCAND]; int ki[NCAND];
#pragma unroll
    for (int s = 0; s < NCAND; ++s) { kv[s] = 3.4e38f; ki[s] = 0x7fffffff; }

    uint32_t aF0[2][4], bF0[2][4];
    uint32_t aF1[2][4], bF1[2][4];

    // ---- persistent A tile: 128 rows x 32 quads, 8 cp16/thread ----
#pragma unroll
    for (int i = 0; i < 8; ++i) {
        const int f = i * 512 + tid;
        const int r = f >> 5, qq = f & 31;
        const uint32_t d = sb + (uint32_t)(r * 512 + (qq >> 3) * 128 +
                                           ((qq & 7) ^ (r & 7)) * 16);
        cp16(d, g_A8 + (size_t)(brow + r) * DD + qq * 16);
    }
    cp_commit();

// B chunk: 128 rows x 256 B, 2048 cp16 = 4 per thread
#define LOAD_B(G) do {                                                      \
    const int _g = (G);                                                     \
    const uint32_t stg = sb + OFF_B + (uint32_t)(_g & 1) * B_T_B;           \
    const int _kt = (_g & 1) * KCHB;                                        \
    const int _jb = jbase + (_g >> 1) * KNT;                                \
    _Pragma("unroll")                                                       \
    for (int i = 0; i < 4; ++i) {                                           \
        const int f = tid + i * 512;                                        \
        const int r = f >> 4, q = f & 15;                                   \
        const uint32_t dofs = (uint32_t)(r * 256 + (q >> 3) * 128 +         \
                                         ((q & 7) ^ (r & 7)) * 16);         \
        cp16(stg + dofs, g_A8 + (size_t)(_jb + r) * DD + _kt + q * 16);     \
    }                                                                       \
    cp_commit();                                                            \
} while (0)

// step S = k32 index within chunk (0..7); A k-step = c*8 + S
#define LOAD_FRAGS(B, S) do {                                               \
    const int _ks = c * 8 + (S);                                            \
    const uint32_t ad = sb + aro + (uint32_t)((_ks >> 2) * 128) + kof4[_ks & 3]; \
    ldsm4(aF##B[0], ad);  ldsm4(aF##B[1], ad + 16 * 512);                   \
    const uint32_t bd = bbase + bro + (uint32_t)(((S) >> 2) * 128) + kof4[(S) & 3]; \
    ldsm4(bF##B[0], bd);  ldsm4(bF##B[1], bd + 16 * 256);                   \
} while (0)

#define MMA_STEP(B) do {                                                    \
    _Pragma("unroll")                                                       \
    for (int mt = 0; mt < 2; ++mt)                                          \
        _Pragma("unroll")                                                   \
        for (int np = 0; np < 2; ++np)                                      \
            _Pragma("unroll")                                               \
            for (int sel = 0; sel < 2; ++sel)                               \
                qmma(acc[mt][np * 2 + sel], aF##B[mt],                      \
                     bF##B[np][sel], bF##B[np][sel + 2]);                   \
} while (0)

    // prologue: B chunk 0 (A group + B0 retire at the first wait0)
    LOAD_B(0);

    for (int t = 0; t < NTILES; ++t) {
        const int jb = jbase + t * KNT;

        float acc[2][4][4];
#pragma unroll
        for (int a = 0; a < 2; ++a)
#pragma unroll
            for (int b = 0; b < 4; ++b)
#pragma unroll
                for (int c = 0; c < 4; ++c) acc[a][b][c] = 0.0f;

        for (int c = 0; c < NCH; ++c) {
            const int g = t * NCH + c;
            cp_wait0();              // B(g) landed (issued one chunk earlier)
            __syncthreads();         // all warps done reading stage (g-1)&1
            if (g + 1 < NCHT) LOAD_B(g + 1);   // writes stage (g+1)&1 != g&1

            const uint32_t bbase = sb + OFF_B + (uint32_t)(g & 1) * B_T_B;
            // 8 k32 steps, fragment double-buffered
            LOAD_FRAGS(0, 0);
            LOAD_FRAGS(1, 1);
            MMA_STEP(0);
            LOAD_FRAGS(0, 2);
            MMA_STEP(1);
            LOAD_FRAGS(1, 3);
            MMA_STEP(0);
            LOAD_FRAGS(0, 4);
            MMA_STEP(1);
            LOAD_FRAGS(1, 5);
            MMA_STEP(0);
            LOAD_FRAGS(0, 6);
            MMA_STEP(1);
            LOAD_FRAGS(1, 7);
            MMA_STEP(0);
            MMA_STEP(1);
        }

        // ---- stage dot values + sq[j] to smem ----
        if (tid < 128)
            *(float*)(smc + OFF_SQS + tid * 4) = g_sqn[jb + tid];
        {
            float* Dst = (float*)(smc + OFF_D);
            const int m0 = wm * 32 + (lane >> 2);
            const int n0 = wn * 32 + (lane & 3) * 2;
#pragma unroll
            for (int mt = 0; mt < 2; ++mt)
#pragma unroll
                for (int nt = 0; nt < 4; ++nt) {
                    *(float2*)(Dst + (m0 + mt * 16    ) * DSTRIDE + n0 + nt * 8) =
                        make_float2(acc[mt][nt][0], acc[mt][nt][1]);
                    *(float2*)(Dst + (m0 + mt * 16 + 8) * DSTRIDE + n0 + nt * 8) =
                        make_float2(acc[mt][nt][2], acc[mt][nt][3]);
                }
        }
        __syncthreads();

        // ---- selection: 4 threads per row, 32 cols each, register lists ----
        {
            const int row = tid & 127, qtr = tid >> 7;
            const int grow = brow + row;
            const float4* Dp  = (const float4*)((const float*)(smc + OFF_D) +
                                                row * DSTRIDE + qtr * 32);
            const float4* sqp = (const float4*)((const float*)(smc + OFF_SQS) +
                                                qtr * 32);
            const int j0 = jb + qtr * 32;
#pragma unroll
            for (int n4 = 0; n4 < 8; ++n4) {
                float4 d4 = Dp[n4];
                float4 s4 = sqp[n4];
                const int j = j0 + n4 * 4;
                float v0 = s4.x - 2.0f * d4.x;
                float v1 = s4.y - 2.0f * d4.y;
                float v2 = s4.z - 2.0f * d4.z;
                float v3 = s4.w - 2.0f * d4.w;
                if (j + 0 != grow) topk_insert<NCAND>(kv, ki, v0, j + 0);
                if (j + 1 != grow) topk_insert<NCAND>(kv, ki, v1, j + 1);
                if (j + 2 != grow) topk_insert<NCAND>(kv, ki, v2, j + 2);
                if (j + 3 != grow) topk_insert<NCAND>(kv, ki, v3, j + 3);
            }
        }
        // next D write happens after the next tile's chunk barriers -> safe
    }

    // ---- merge the 4 per-row lists through smem, write candidates ----------
    __syncthreads();
    {
        float* mv = (float*)(smc + OFF_D);
        int*   mi = (int*)(smc + OFF_D) + 512 * NCAND;
#pragma unroll
        for (int s = 0; s < NCAND; ++s) {
            mv[tid * NCAND + s] = kv[s];
            mi[tid * NCAND + s] = ki[s];
        }
    }
    __syncthreads();
    if (tid < 128) {
        float* mv = (float*)(smc + OFF_D);
        int*   mi = (int*)(smc + OFF_D) + 512 * NCAND;
#pragma unroll
        for (int o = 1; o < 4; ++o) {
            const int b = (tid + o * 128) * NCAND;
#pragma unroll
            for (int s = 0; s < NCAND; ++s)
                topk_insert<NCAND>(kv, ki, mv[b + s], mi[b + s]);
        }
        const int grow = brow + tid;
        const int base = (grow * 2 + half) * NCAND;
#pragma unroll
        for (int s = 0; s < NCAND; ++s) g_cand_i[base + s] = ki[s];
    }
#undef LOAD_B
#undef LOAD_FRAGS
#undef MMA_STEP
}

// ========= exact fp32 rescore of 16 candidates -> top-5 =====================
__global__ __launch_bounds__(512, 1) void rescore_kernel(const float* __restrict__ A) {
    const int row = blockIdx.x;
    const int w = threadIdx.x >> 5, lane = threadIdx.x & 31;  // 16 warps
    __shared__ float sa[DD];
    __shared__ float sv[16];
    __shared__ int   si[16];
    if (threadIdx.x < DD) sa[threadIdx.x] = A[(size_t)row * DD + threadIdx.x];
    __syncthreads();
    const int j = g_cand_i[row * 16 + w];
    const float* aj = A + (size_t)j * DD;
    float dot = 0.0f;
#pragma unroll
    for (int k = 0; k < 16; ++k) dot += sa[lane + k * 32] * aj[lane + k * 32];
#pragma unroll
    for (int off = 16; off > 0; off >>= 1) dot += __shfl_xor_sync(0xffffffffu, dot, off);
    if (lane == 0) { sv[w] = g_sqn[j] - 2.0f * dot; si[w] = j; }
    __syncthreads();
    if (threadIdx.x == 0) {
        float bv[KNN]; int bi[KNN];
#pragma unroll
        for (int s = 0; s < KNN; ++s) { bv[s] = 3.4e38f; bi[s] = 0x7fffffff; }
        for (int e = 0; e < 16; ++e) {
            float v = sv[e]; int id = si[e];
            if (kless(v, id, bv[KNN - 1], bi[KNN - 1])) {
                bv[KNN - 1] = v; bi[KNN - 1] = id;
#pragma unroll
                for (int p = KNN - 1; p > 0; --p) {
                    if (kless(bv[p], bi[p], bv[p - 1], bi[p - 1])) {
                        float fv = bv[p]; bv[p] = bv[p - 1]; bv[p - 1] = fv;
                        int   iv = bi[p]; bi[p] = bi[p - 1]; bi[p - 1] = iv;
                    }
                }
            }
        }
#pragma unroll
        for (int s = 0; s < KNN; ++s) g_nn[row * KNN + s] = bi[s];
    }
}

// ===================== SMOTE interpolation ==================================
__global__ void populate_kernel(const float* __restrict__ A,
                                const float* __restrict__ gaps,
                                const unsigned int* __restrict__ cw,
                                float* __restrict__ out) {
    int o = blockIdx.x;
    int i = o >> 2;
    float g = gaps[o];
    int widx = g_choice_is32 ? o : (o << 1);
    int c  = (int)cw[widx];
    int nb = g_nn[i * KNN + c];
    const float4* ai = reinterpret_cast<const float4*>(A + (size_t)i  * DD);
    const float4* an = reinterpret_cast<const float4*>(A + (size_t)nb * DD);
    float4* op = reinterpret_cast<float4*>(out) + (size_t)o * (DD / 4);
    int t = threadIdx.x;
    float4 a = ai[t], b = an[t];
    float4 r;
    r.x = a.x + g * (b.x - a.x);
    r.y = a.y + g * (b.y - a.y);
    r.z = a.z + g * (b.z - a.z);
    r.w = a.w + g * (b.w - a.w);
    op[t] = r;
}

// ============================================================================
extern "C" void kernel_launch(void* const* d_in, const int* in_sizes, int n_in,
                              void* d_out, int out_size) {
    const float* A         = (const float*)d_in[0];
    const float* gaps      = (const float*)d_in[1];
    const unsigned int* cw = (const unsigned int*)d_in[2];
    float* out             = (float*)d_out;

    cudaFuncSetAttribute(knn_mma_kernel,
                         cudaFuncAttributeMaxDynamicSharedMemorySize, SMEM_TOTAL);

    convert_kernel<<<TN * DD / 4 / 256, 256>>>(A);
    sqnorm_kernel<<<TN, 128>>>(A);
    detect_kernel<<<64, 256>>>(cw);
    knn_mma_kernel<<<128, 512, SMEM_TOTAL>>>();
    rescore_kernel<<<TN, 512>>>(A);
    populate_kernel<<<TN * NPER, 128>>>(A, gaps, cw, out);
}